// round 7
// baseline (speedup 1.0000x reference)
#include <cuda_runtime.h>
#include <cuda_bf16.h>
#include <cstdint>

// Dequant: out[r][c] = (float)q[r][c] * row_stats[r] * (1/127)
// ROWS = COLS = 8192, int32 in -> fp32 out. Pure streaming: 512 MiB total.
//
// R7: same as measured-best R3/R6 layout (one block == one row, 256 thr x
// 8 int4, MLP=8 front-batched loads with .cs) but stores use WRITE-THROUGH
// (__stwt -> STG.E.WT): the write stream passes through L2 without leaving
// dirty lines, removing dirty-eviction bookkeeping from the LTS, which is
// the saturated resource (~82% DRAM-active, LTS-cap bound).
// Store-policy matrix so far: .cs 73.9-74.7us | default 75.5us | .wt = this.

#define VPT 8                         // int4 vectors per thread
#define TPB 256                       // TPB*VPT = 2048 vecs = 8192 cols = 1 row

__global__ void __launch_bounds__(TPB, 6)
dequant_kernel(const int4* __restrict__ q,
               const float* __restrict__ row_stats,
               float4* __restrict__ out)
{
    // Uniform per-block scale: block r handles row r.
    const float scale = __ldg(&row_stats[blockIdx.x]) * (1.0f / 127.0f);

    const int base = blockIdx.x * (TPB * VPT) + threadIdx.x;

    // Front-batch 8 independent LDG.E.128 (MLP=8), streaming hint.
    int4 v[VPT];
#pragma unroll
    for (int j = 0; j < VPT; j++)
        v[j] = __ldcs(&q[base + j * TPB]);

#pragma unroll
    for (int j = 0; j < VPT; j++) {
        float4 r;
        r.x = (float)v[j].x * scale;
        r.y = (float)v[j].y * scale;
        r.z = (float)v[j].z * scale;
        r.w = (float)v[j].w * scale;
        __stwt(&out[base + j * TPB], r);   // write-through: no dirty L2 lines
    }
}

extern "C" void kernel_launch(void* const* d_in, const int* in_sizes, int n_in,
                              void* d_out, int out_size)
{
    const int4*  q         = (const int4*)d_in[0];   // int32 [8192,8192]
    const float* row_stats = (const float*)d_in[1];  // fp32  [8192]
    float4*      out       = (float4*)d_out;

    const int rows = in_sizes[1];                    // 8192 blocks, one per row

    dequant_kernel<<<rows, TPB>>>(q, row_stats, out);
}

// round 8
// speedup vs baseline: 1.0117x; 1.0117x over previous
#include <cuda_runtime.h>
#include <cuda_bf16.h>
#include <cstdint>

// Dequant: out[r][c] = (float)q[r][c] * row_stats[r] * (1/127)
// ROWS = COLS = 8192, int32 in -> fp32 out. Pure streaming: 512 MiB total.
//
// FINAL — measured-best config across the full R2-R7 sweep:
//  - one block == one row: 256 threads x 8 int4 vecs = 2048 vecs = 8192 cols,
//    so the row scale is uniform per block (single __ldg, no per-vec ALU).
//  - 8 front-batched independent LDG.E.128 per thread (MLP=8), stride 4 KB.
//  - streaming .cs hints on BOTH loads and stores.
// Measured store-policy matrix (kernel us): .cs 73.9-74.7 | contiguous-warp
// 75.2 | .wt 75.3 | default 75.5. MLP 4 vs 8: 74.5 vs 73.9.
// All variants sit at 80-82% DRAM-active (~6.4-6.5 TB/s) = the B300 mixed
// 1:1 read/write HBM-stream ceiling; traffic is fixed by the I/O contract,
// so this kernel is at the roofline.

#define VPT 8                         // int4 vectors per thread
#define TPB 256                       // TPB*VPT = 2048 vecs = 8192 cols = 1 row

__global__ void __launch_bounds__(TPB, 6)
dequant_kernel(const int4* __restrict__ q,
               const float* __restrict__ row_stats,
               float4* __restrict__ out)
{
    // Uniform per-block scale: block r handles row r.
    const float scale = __ldg(&row_stats[blockIdx.x]) * (1.0f / 127.0f);

    const int base = blockIdx.x * (TPB * VPT) + threadIdx.x;

    // Front-batch 8 independent LDG.E.128 (MLP=8), streaming hint.
    int4 v[VPT];
#pragma unroll
    for (int j = 0; j < VPT; j++)
        v[j] = __ldcs(&q[base + j * TPB]);

#pragma unroll
    for (int j = 0; j < VPT; j++) {
        float4 r;
        r.x = (float)v[j].x * scale;
        r.y = (float)v[j].y * scale;
        r.z = (float)v[j].z * scale;
        r.w = (float)v[j].w * scale;
        __stcs(&out[base + j * TPB], r);   // streaming store (measured best)
    }
}

extern "C" void kernel_launch(void* const* d_in, const int* in_sizes, int n_in,
                              void* d_out, int out_size)
{
    const int4*  q         = (const int4*)d_in[0];   // int32 [8192,8192]
    const float* row_stats = (const float*)d_in[1];  // fp32  [8192]
    float4*      out       = (float4*)d_out;

    const int rows = in_sizes[1];                    // 8192 blocks, one per row

    dequant_kernel<<<rows, TPB>>>(q, row_stats, out);
}